// round 4
// baseline (speedup 1.0000x reference)
#include <cuda_runtime.h>
#include <math.h>

#define HW    80
#define NPIX  6400          // 80*80
#define NB    2
#define NL    4
#define NC    64
#define NPAIR 32            // B*L*L
#define NIMG  8             // B*L

// ---------------- scratch (static __device__, no allocations) ----------------
__device__ float g_minv[NPAIR * 6];
__device__ float g_mask[NPAIR * NPIX];
__device__ float g_masksum[NIMG * NPIX];
__device__ float g_y[NIMG * NC * NPIX];        // y (iter input) / h1
__device__ float g_nbr[NPAIR * NC * NPIX];     // warped neighbors
__device__ float g_convn[NPAIR * NC * NPIX];   // conv(neighbor)
__device__ float g_ego[NIMG * NC * NPIX];      // conv(ego)+bias
__device__ float g_agg[NIMG * NC * NPIX];      // masked mean
__device__ float g_gru[NIMG * 2 * NC * NPIX];  // [update|cand] logits
__device__ float g_wnbr[64 * 64 * 9];
__device__ float g_wego[64 * 64 * 9];
__device__ float g_wgru[128 * 128 * 9];
__device__ float g_bgru[128];

// accurate activations (avoid fast-math tanh.approx)
__device__ __forceinline__ float sigmoid_acc(float u) {
    return 1.0f / (1.0f + expf(-u));
}
__device__ __forceinline__ float tanh_acc(float x) {
    float a = fabsf(x);
    float e = expf(-2.0f * a);
    float t = (1.0f - e) / (1.0f + e);
    return copysignf(t, x);
}

// ---------------- affine inverse: replicate reference fp32 arithmetic -------
// Reference: t[...,2] /= 0.8;  T = [R | center - R@center + t2];
// Minv = inv([[T],[0,0,1]]) via LU (no pivot swap occurs: |cos|>|sin| here)
// with reciprocal-scaled multipliers (LAPACK sgetf2), FMA Schur updates,
// and triangular solves against I with IEEE division + FMA-chain updates.
// All ops pinned with _rn intrinsics (immune to fast-math contraction).
__global__ void k_minv(const float* __restrict__ P) {
    int p = threadIdx.x;                 // 0..31  (b*16 + i*4 + j)
    if (p >= NPAIR) return;
    const float* M = P + p * 16;         // 4x4 row-major
    float a = M[0], b = M[1];
    float c = M[4], d = M[5];
    float txs = __fdiv_rn(M[3], 0.8f);
    float tys = __fdiv_rn(M[7], 0.8f);
    const float cx = 40.0f, cy = 40.0f;
    // einsum('nij,j->ni', R, center): multiply then reduce (mul,mul,add)
    float dot0 = __fadd_rn(__fmul_rn(a, cx), __fmul_rn(b, cy));
    float dot1 = __fadd_rn(__fmul_rn(c, cx), __fmul_rn(d, cy));
    // trans = (center - dot) + t2   (left-assoc)
    float Tx = __fadd_rn(__fsub_rn(cx, dot0), txs);
    float Ty = __fadd_rn(__fsub_rn(cy, dot1), tys);

    // LU of [[a,b,Tx],[c,d,Ty],[0,0,1]], pivot = a (no row swap)
    float ra  = __fdiv_rn(1.0f, a);          // sgetf2 reciprocal scale
    float l10 = __fmul_rn(c, ra);
    float u22 = __fmaf_rn(-l10, b, d);       // Schur update (fma)
    float u23 = __fmaf_rn(-l10, Tx, Ty);

    // Solve A X = I: forward (unit L), back (U with division)
    // col0: y=[1,-l10,0]
    float x1_0 = __fdiv_rn(-l10, u22);
    float x0_0 = __fdiv_rn(__fmaf_rn(-b, x1_0, 1.0f), a);
    // col1: y=[0,1,0]
    float x1_1 = __fdiv_rn(1.0f, u22);
    float x0_1 = __fdiv_rn(__fmul_rn(-b, x1_1), a);
    // col2: y=[0,0,1], x2=1
    float x1_2 = __fdiv_rn(-u23, u22);
    float x0_2 = __fdiv_rn(__fmaf_rn(-b, x1_2, -Tx), a);

    float* o = g_minv + p * 6;
    o[0] = x0_0; o[1] = x0_1; o[2] = x0_2;   // Minv row 0
    o[3] = x1_0; o[4] = x1_1; o[5] = x1_2;   // Minv row 1
}

// pinned-order coordinate transform: s = ((m0*x) fma m1*y) + m2
__device__ __forceinline__ float coordx(const float* mv, float x, float y) {
    float s = __fmul_rn(mv[0], x);
    s = __fmaf_rn(mv[1], y, s);
    return __fadd_rn(s, mv[2]);
}
__device__ __forceinline__ float coordy(const float* mv, float x, float y) {
    float s = __fmul_rn(mv[3], x);
    s = __fmaf_rn(mv[4], y, s);
    return __fadd_rn(s, mv[5]);
}

// ---------------- nearest-warp validity mask ----------------
__global__ void k_mask() {
    int pair = blockIdx.y;
    int p = blockIdx.x * 256 + threadIdx.x;
    if (p >= NPIX) return;
    const float* mv = g_minv + pair * 6;
    float x = (float)(p % HW), y = (float)(p / HW);
    float sx = coordx(mv, x, y);
    float sy = coordy(mv, x, y);
    int ix = (int)rintf(sx);             // half-to-even, matches jnp.round
    int iy = (int)rintf(sy);
    g_mask[pair * NPIX + p] =
        (ix >= 0 && ix < HW && iy >= 0 && iy < HW) ? 1.0f : 0.0f;
}

__global__ void k_masksum() {
    int bj = blockIdx.y;                 // b*4 + j
    int p = blockIdx.x * 256 + threadIdx.x;
    if (p >= NPIX) return;
    int b = bj >> 2, j = bj & 3;
    float s = 0.0f;
#pragma unroll
    for (int i = 0; i < 4; i++)
        s += g_mask[((b * 4 + i) * 4 + j) * NPIX + p];
    g_masksum[bj * NPIX + p] = s;
}

// ---------------- initial transform: y[c,h,w] = x[c, 79-w, h] ----------------
__global__ void k_transform(const float* __restrict__ x) {
    int idx = blockIdx.x * 256 + threadIdx.x;   // over NIMG*NC*NPIX
    int p = idx % NPIX;
    int c = (idx / NPIX) & 63;
    int bl = idx / (NPIX * 64);
    int h = p / HW, w = p % HW;
    g_y[idx] = x[(bl * 64 + c) * NPIX + (HW - 1 - w) * HW + h];
}

// ---------------- bilinear warp of y[b,i] by T[pair] ----------------
__global__ void k_warp() {
    int pair = blockIdx.y;
    int p = blockIdx.x * 256 + threadIdx.x;
    if (p >= NPIX) return;
    int b = pair >> 4;
    int i = (pair >> 2) & 3;
    const float* mv = g_minv + pair * 6;
    float x = (float)(p % HW), y = (float)(p / HW);
    float sx = coordx(mv, x, y);
    float sy = coordy(mv, x, y);
    float x0f = floorf(sx), y0f = floorf(sy);
    float fx = __fsub_rn(sx, x0f), fy = __fsub_rn(sy, y0f);
    int x0 = (int)x0f, y0 = (int)y0f;
    int x1 = x0 + 1, y1 = y0 + 1;
    int cx0 = min(max(x0, 0), HW - 1), cx1 = min(max(x1, 0), HW - 1);
    int cy0 = min(max(y0, 0), HW - 1), cy1 = min(max(y1, 0), HW - 1);
    float vx0 = (x0 >= 0 && x0 < HW) ? 1.0f : 0.0f;
    float vx1 = (x1 >= 0 && x1 < HW) ? 1.0f : 0.0f;
    float vy0 = (y0 >= 0 && y0 < HW) ? 1.0f : 0.0f;
    float vy1 = (y1 >= 0 && y1 < HW) ? 1.0f : 0.0f;
    float gx = __fsub_rn(1.0f, fx), gy = __fsub_rn(1.0f, fy);
    float w00 = __fmul_rn(__fmul_rn(vx0, vy0), __fmul_rn(gx, gy));
    float w10 = __fmul_rn(__fmul_rn(vx1, vy0), __fmul_rn(fx, gy));
    float w01 = __fmul_rn(__fmul_rn(vx0, vy1), __fmul_rn(gx, fy));
    float w11 = __fmul_rn(__fmul_rn(vx1, vy1), __fmul_rn(fx, fy));
    int i00 = cy0 * HW + cx0, i10 = cy0 * HW + cx1;
    int i01 = cy1 * HW + cx0, i11 = cy1 * HW + cx1;
    const float* src = g_y + (b * 4 + i) * 64 * NPIX;
    float* dst = g_nbr + pair * 64 * NPIX;
#pragma unroll 4
    for (int c = 0; c < 64; c++) {
        const float* sc = src + c * NPIX;
        float v = __fmul_rn(w00, sc[i00]);
        v = __fadd_rn(v, __fmul_rn(w10, sc[i10]));
        v = __fadd_rn(v, __fmul_rn(w01, sc[i01]));
        v = __fadd_rn(v, __fmul_rn(w11, sc[i11]));
        dst[c * NPIX + p] = v;
    }
}

// ---------------- tiled direct 3x3 conv (SAME), NCHW fp32 ----------------
// Block: 256 thr. Tile 16x16 pixels x 64 cout. Thread: 4 pixels x 16 cout.
template <int CIN>
__global__ __launch_bounds__(256, 2)
void conv3x3_k(const float* __restrict__ inA, int inA_stride,
               const float* __restrict__ inB, int inB_stride, int splitC,
               const float* __restrict__ Wt,   // [COUT][CIN][9] prepacked
               const float* __restrict__ bias, // may be null
               float* __restrict__ outp, int out_stride) {
    __shared__ float sX[8][18][20];   // padded rows -> conflict free
    __shared__ float sW[64 * 8 * 9];
    const int img = blockIdx.z;
    const int co0 = blockIdx.y * 64;
    const int tx = blockIdx.x % 5, ty = blockIdx.x / 5;
    const int w0 = tx * 16, h0 = ty * 16;
    const int t = threadIdx.x;
    const int s = t & 63;
    const int wl = s & 15;     // pixel col in tile
    const int hq = s >> 4;     // row quad 0..3
    const int cg = t >> 6;     // cout group 0..3 (16 each)

    float acc[4][16];
#pragma unroll
    for (int k = 0; k < 4; k++)
#pragma unroll
        for (int j = 0; j < 16; j++) acc[k][j] = 0.0f;

    for (int cin0 = 0; cin0 < CIN; cin0 += 8) {
        const float* src;
        int cbase;
        if (cin0 < splitC) { src = inA + (long)img * inA_stride; cbase = cin0; }
        else               { src = inB + (long)img * inB_stride; cbase = cin0 - splitC; }
        // stage input tile with halo: 8ci x 18 x 18
        for (int idx = t; idx < 8 * 18 * 18; idx += 256) {
            int ci = idx / 324, rem = idx % 324;
            int r = rem / 18, c = rem % 18;
            int gh = h0 - 1 + r, gw = w0 - 1 + c;
            float v = 0.0f;
            if (gh >= 0 && gh < HW && gw >= 0 && gw < HW)
                v = src[(cbase + ci) * NPIX + gh * HW + gw];
            sX[ci][r][c] = v;
        }
        // stage weights: 64co x 8ci x 9
        for (int idx = t; idx < 64 * 8 * 9; idx += 256) {
            int co = idx / 72, rem = idx % 72;
            sW[co * 72 + rem] = Wt[(long)(co0 + co) * CIN * 9 + cin0 * 9 + rem];
        }
        __syncthreads();
#pragma unroll 1
        for (int ci = 0; ci < 8; ci++) {
            float xr[6][3];
#pragma unroll
            for (int rr = 0; rr < 6; rr++)
#pragma unroll
                for (int cc = 0; cc < 3; cc++)
                    xr[rr][cc] = sX[ci][hq * 4 + rr][wl + cc];
            const float* wp = &sW[(cg * 16) * 72 + ci * 9];
#pragma unroll
            for (int j = 0; j < 16; j++) {
#pragma unroll
                for (int tap = 0; tap < 9; tap++) {
                    float wv = wp[j * 72 + tap];
                    int r = tap / 3, c = tap % 3;
#pragma unroll
                    for (int k = 0; k < 4; k++)
                        acc[k][j] = fmaf(wv, xr[k + r][c], acc[k][j]);
                }
            }
        }
        __syncthreads();
    }
#pragma unroll
    for (int j = 0; j < 16; j++) {
        int co = co0 + cg * 16 + j;
        float bv = bias ? bias[co] : 0.0f;
#pragma unroll
        for (int k = 0; k < 4; k++) {
            int h = h0 + hq * 4 + k, w = w0 + wl;
            outp[(long)img * out_stride + co * NPIX + h * HW + w] = acc[k][j] + bv;
        }
    }
}

// ---------------- masked mean over i ----------------
__global__ void k_agg() {
    int bj = blockIdx.y;
    int p = blockIdx.x * 256 + threadIdx.x;
    if (p >= NPIX) return;
    int b = bj >> 2, j = bj & 3;
    float ms = g_masksum[bj * NPIX + p];
    float m[4];
#pragma unroll
    for (int i = 0; i < 4; i++)
        m[i] = g_mask[((b * 4 + i) * 4 + j) * NPIX + p];
#pragma unroll 4
    for (int c = 0; c < 64; c++) {
        float v = ms * g_ego[bj * 64 * NPIX + c * NPIX + p];
#pragma unroll
        for (int i = 0; i < 4; i++)
            v += m[i] * g_convn[((b * 4 + i) * 4 + j) * 64 * NPIX + c * NPIX + p];
        g_agg[bj * 64 * NPIX + c * NPIX + p] = 0.25f * v;
    }
}

// ---------------- GRU pointwise: y <- sigmoid(u)*tanh(c) ----------------
__global__ void k_pointwise() {
    int idx = blockIdx.x * 256 + threadIdx.x;   // NIMG*NC*NPIX
    int p = idx % NPIX;
    int c = (idx / NPIX) & 63;
    int bl = idx / (NPIX * 64);
    float u  = g_gru[bl * 128 * NPIX + c * NPIX + p];
    float cd = g_gru[bl * 128 * NPIX + (64 + c) * NPIX + p];
    g_y[idx] = sigmoid_acc(u) * tanh_acc(cd);
}

// ---------------- weight prepack ----------------
__global__ void k_prepack(const float* __restrict__ msg_w,
                          const float* __restrict__ gates_w,
                          const float* __restrict__ gates_b,
                          const float* __restrict__ can_w,
                          const float* __restrict__ can_b) {
    int idx = blockIdx.x * 256 + threadIdx.x;
    if (idx < 36864) {                         // msg split
        int co = idx / 576, rem = idx % 576;   // rem = ci*9+tap, ci<64
        g_wnbr[idx] = msg_w[co * 1152 + rem];           // cin 0..63
        g_wego[idx] = msg_w[co * 1152 + 576 + rem];     // cin 64..127
        return;
    }
    int k = idx - 36864;
    if (k < 147456) {                          // gru stacked [update|cand]
        int co = k / 1152, rem = k % 1152;     // rem = ci*9+tap, ci<128
        g_wgru[k] = (co < 64) ? gates_w[(64 + co) * 1728 + rem]
                              : can_w[(co - 64) * 1728 + rem];
        return;
    }
    k -= 147456;
    if (k < 128)
        g_bgru[k] = (k < 64) ? gates_b[64 + k] : can_b[k - 64];
}

// ---------------- output: out[b,h,w,o] = mlp_w[o,:]·h1[b,0,:,w,79-h]+mlp_b ----
__global__ void k_out(const float* __restrict__ mlp_w,
                      const float* __restrict__ mlp_b,
                      float* __restrict__ out) {
    __shared__ float sW[64 * 65];     // sW[c*65+o] = mlp_w[o*64+c]
    __shared__ float sx[4][64];
    int t = threadIdx.x;
    for (int idx = t; idx < 4096; idx += 256) {
        int o = idx >> 6, c = idx & 63;
        sW[c * 65 + o] = mlp_w[idx];
    }
    int pix = t >> 6, o = t & 63;
    int pp = blockIdx.x * 4 + pix;    // 0 .. 2*NPIX-1
    int b = pp / NPIX, pr = pp % NPIX;
    int h = pr / HW, w = pr % HW;
    int q = w * HW + (HW - 1 - h);
    sx[pix][o] = g_y[(b * 4) * 64 * NPIX + o * NPIX + q];   // feats[:,0]
    __syncthreads();
    float acc = mlp_b[o];
#pragma unroll 8
    for (int c = 0; c < 64; c++)
        acc = fmaf(sx[pix][c], sW[c * 65 + o], acc);
    out[pp * 64 + o] = acc;
}

// ---------------- host orchestration ----------------
extern "C" void kernel_launch(void* const* d_in, const int* in_sizes, int n_in,
                              void* d_out, int out_size) {
    const float* x       = (const float*)d_in[0];
    const float* pt      = (const float*)d_in[2];
    const float* msg_w   = (const float*)d_in[4];
    const float* msg_b   = (const float*)d_in[5];
    const float* gates_w = (const float*)d_in[6];
    const float* gates_b = (const float*)d_in[7];
    const float* can_w   = (const float*)d_in[8];
    const float* can_b   = (const float*)d_in[9];
    const float* mlp_w   = (const float*)d_in[10];
    const float* mlp_b   = (const float*)d_in[11];

    float *p_y, *p_nbr, *p_convn, *p_ego, *p_agg, *p_gru;
    float *p_wnbr, *p_wego, *p_wgru, *p_bgru;
    cudaGetSymbolAddress((void**)&p_y, g_y);
    cudaGetSymbolAddress((void**)&p_nbr, g_nbr);
    cudaGetSymbolAddress((void**)&p_convn, g_convn);
    cudaGetSymbolAddress((void**)&p_ego, g_ego);
    cudaGetSymbolAddress((void**)&p_agg, g_agg);
    cudaGetSymbolAddress((void**)&p_gru, g_gru);
    cudaGetSymbolAddress((void**)&p_wnbr, g_wnbr);
    cudaGetSymbolAddress((void**)&p_wego, g_wego);
    cudaGetSymbolAddress((void**)&p_wgru, g_wgru);
    cudaGetSymbolAddress((void**)&p_bgru, g_bgru);

    k_minv<<<1, 32>>>(pt);
    k_prepack<<<(36864 + 147456 + 128 + 255) / 256, 256>>>(msg_w, gates_w,
                                                           gates_b, can_w, can_b);
    k_mask<<<dim3(25, NPAIR), 256>>>();
    k_masksum<<<dim3(25, NIMG), 256>>>();
    k_transform<<<(NIMG * NC * NPIX) / 256, 256>>>(x);

    for (int it = 0; it < 2; it++) {
        k_warp<<<dim3(25, NPAIR), 256>>>();
        // conv(neighbors): 32 imgs, 64->64, no bias
        conv3x3_k<64><<<dim3(25, 1, NPAIR), 256>>>(
            p_nbr, 64 * NPIX, p_nbr, 0, 64, p_wnbr, nullptr, p_convn, 64 * NPIX);
        // conv(ego): 8 imgs, 64->64, + msg_b
        conv3x3_k<64><<<dim3(25, 1, NIMG), 256>>>(
            p_y, 64 * NPIX, p_y, 0, 64, p_wego, msg_b, p_ego, 64 * NPIX);
        k_agg<<<dim3(25, NIMG), 256>>>();
        // fused GRU conv: [y|agg] 128 -> [update|cand] 128
        conv3x3_k<128><<<dim3(25, 2, NIMG), 256>>>(
            p_y, 64 * NPIX, p_agg, 64 * NPIX, 64, p_wgru, p_bgru, p_gru,
            128 * NPIX);
        k_pointwise<<<(NIMG * NC * NPIX) / 256, 256>>>();
    }

    k_out<<<2 * NPIX / 4, 256>>>(mlp_w, mlp_b, (float*)d_out);
}

// round 5
// speedup vs baseline: 1.2814x; 1.2814x over previous
#include <cuda_runtime.h>
#include <math.h>

#define HW    80
#define NPIX  6400          // 80*80
#define NB    2
#define NL    4
#define NC    64
#define NPAIR 32            // B*L*L
#define NIMG  8             // B*L

typedef unsigned long long ull;

// ---------------- scratch (static __device__, no allocations) ----------------
__device__ float g_minv[NPAIR * 6];
__device__ float g_mask[NPAIR * NPIX];
__device__ float g_masksum[NIMG * NPIX];
__device__ float g_y[NIMG * NC * NPIX];        // y (iter input) / h1
__device__ float g_nbr[NPAIR * NC * NPIX];     // warped neighbors
__device__ float g_convn[NPAIR * NC * NPIX];   // conv(neighbor)
__device__ float g_ego[NIMG * NC * NPIX];      // conv(ego)+bias
__device__ float g_agg[NIMG * NC * NPIX];      // masked mean
__device__ float g_gru[NIMG * 2 * NC * NPIX];  // [update|cand] logits
__device__ float2 g_wnbr2[32 * 64 * 9];        // [co2][cin][tap] cout-paired
__device__ float2 g_wego2[32 * 64 * 9];
__device__ float2 g_wgru2[64 * 128 * 9];
__device__ float g_bgru[128];

// ---------------- packed fp32x2 helpers (sm_103a FFMA2) ----------------
__device__ __forceinline__ void fma2(ull& d, ull a, ull b) {
    asm("fma.rn.f32x2 %0, %1, %2, %0;" : "+l"(d) : "l"(a), "l"(b));
}
__device__ __forceinline__ ull bcast2(float v) {
    ull r;
    asm("mov.b64 %0, {%1, %1};" : "=l"(r) : "f"(v));
    return r;
}
__device__ __forceinline__ float2 unpack2(ull v) {
    float2 f;
    asm("mov.b64 {%0, %1}, %2;" : "=f"(f.x), "=f"(f.y) : "l"(v));
    return f;
}

// accurate activations (avoid fast-math tanh.approx)
__device__ __forceinline__ float sigmoid_acc(float u) {
    return 1.0f / (1.0f + expf(-u));
}
__device__ __forceinline__ float tanh_acc(float x) {
    float a = fabsf(x);
    float e = expf(-2.0f * a);
    float t = (1.0f - e) / (1.0f + e);
    return copysignf(t, x);
}

// ---------------- affine inverse: replicate reference fp32 arithmetic -------
__global__ void k_minv(const float* __restrict__ P) {
    int p = threadIdx.x;                 // 0..31  (b*16 + i*4 + j)
    if (p >= NPAIR) return;
    const float* M = P + p * 16;         // 4x4 row-major
    float a = M[0], b = M[1];
    float c = M[4], d = M[5];
    float txs = __fdiv_rn(M[3], 0.8f);
    float tys = __fdiv_rn(M[7], 0.8f);
    const float cx = 40.0f, cy = 40.0f;
    float dot0 = __fadd_rn(__fmul_rn(a, cx), __fmul_rn(b, cy));
    float dot1 = __fadd_rn(__fmul_rn(c, cx), __fmul_rn(d, cy));
    float Tx = __fadd_rn(__fsub_rn(cx, dot0), txs);
    float Ty = __fadd_rn(__fsub_rn(cy, dot1), tys);

    // LU (no pivot swap: |cos|>|sin| always here)
    float ra  = __fdiv_rn(1.0f, a);
    float l10 = __fmul_rn(c, ra);
    float u22 = __fmaf_rn(-l10, b, d);
    float u23 = __fmaf_rn(-l10, Tx, Ty);

    float x1_0 = __fdiv_rn(-l10, u22);
    float x0_0 = __fdiv_rn(__fmaf_rn(-b, x1_0, 1.0f), a);
    float x1_1 = __fdiv_rn(1.0f, u22);
    float x0_1 = __fdiv_rn(__fmul_rn(-b, x1_1), a);
    float x1_2 = __fdiv_rn(-u23, u22);
    float x0_2 = __fdiv_rn(__fmaf_rn(-b, x1_2, -Tx), a);

    float* o = g_minv + p * 6;
    o[0] = x0_0; o[1] = x0_1; o[2] = x0_2;
    o[3] = x1_0; o[4] = x1_1; o[5] = x1_2;
}

__device__ __forceinline__ float coordx(const float* mv, float x, float y) {
    float s = __fmul_rn(mv[0], x);
    s = __fmaf_rn(mv[1], y, s);
    return __fadd_rn(s, mv[2]);
}
__device__ __forceinline__ float coordy(const float* mv, float x, float y) {
    float s = __fmul_rn(mv[3], x);
    s = __fmaf_rn(mv[4], y, s);
    return __fadd_rn(s, mv[5]);
}

// ---------------- nearest-warp validity mask ----------------
__global__ void k_mask() {
    int pair = blockIdx.y;
    int p = blockIdx.x * 256 + threadIdx.x;
    if (p >= NPIX) return;
    const float* mv = g_minv + pair * 6;
    float x = (float)(p % HW), y = (float)(p / HW);
    float sx = coordx(mv, x, y);
    float sy = coordy(mv, x, y);
    int ix = (int)rintf(sx);
    int iy = (int)rintf(sy);
    g_mask[pair * NPIX + p] =
        (ix >= 0 && ix < HW && iy >= 0 && iy < HW) ? 1.0f : 0.0f;
}

__global__ void k_masksum() {
    int bj = blockIdx.y;                 // b*4 + j
    int p = blockIdx.x * 256 + threadIdx.x;
    if (p >= NPIX) return;
    int b = bj >> 2, j = bj & 3;
    float s = 0.0f;
#pragma unroll
    for (int i = 0; i < 4; i++)
        s += g_mask[((b * 4 + i) * 4 + j) * NPIX + p];
    g_masksum[bj * NPIX + p] = s;
}

// ---------------- initial transform: y[c,h,w] = x[c, 79-w, h] ----------------
__global__ void k_transform(const float* __restrict__ x) {
    int idx = blockIdx.x * 256 + threadIdx.x;
    int p = idx % NPIX;
    int c = (idx / NPIX) & 63;
    int bl = idx / (NPIX * 64);
    int h = p / HW, w = p % HW;
    g_y[idx] = x[(bl * 64 + c) * NPIX + (HW - 1 - w) * HW + h];
}

// ---------------- bilinear warp of y[b,i] by T[pair] ----------------
__global__ void k_warp() {
    int pair = blockIdx.y;
    int p = blockIdx.x * 256 + threadIdx.x;
    if (p >= NPIX) return;
    int b = pair >> 4;
    int i = (pair >> 2) & 3;
    const float* mv = g_minv + pair * 6;
    float x = (float)(p % HW), y = (float)(p / HW);
    float sx = coordx(mv, x, y);
    float sy = coordy(mv, x, y);
    float x0f = floorf(sx), y0f = floorf(sy);
    float fx = __fsub_rn(sx, x0f), fy = __fsub_rn(sy, y0f);
    int x0 = (int)x0f, y0 = (int)y0f;
    int x1 = x0 + 1, y1 = y0 + 1;
    int cx0 = min(max(x0, 0), HW - 1), cx1 = min(max(x1, 0), HW - 1);
    int cy0 = min(max(y0, 0), HW - 1), cy1 = min(max(y1, 0), HW - 1);
    float vx0 = (x0 >= 0 && x0 < HW) ? 1.0f : 0.0f;
    float vx1 = (x1 >= 0 && x1 < HW) ? 1.0f : 0.0f;
    float vy0 = (y0 >= 0 && y0 < HW) ? 1.0f : 0.0f;
    float vy1 = (y1 >= 0 && y1 < HW) ? 1.0f : 0.0f;
    float gx = __fsub_rn(1.0f, fx), gy = __fsub_rn(1.0f, fy);
    float w00 = __fmul_rn(__fmul_rn(vx0, vy0), __fmul_rn(gx, gy));
    float w10 = __fmul_rn(__fmul_rn(vx1, vy0), __fmul_rn(fx, gy));
    float w01 = __fmul_rn(__fmul_rn(vx0, vy1), __fmul_rn(gx, fy));
    float w11 = __fmul_rn(__fmul_rn(vx1, vy1), __fmul_rn(fx, fy));
    int i00 = cy0 * HW + cx0, i10 = cy0 * HW + cx1;
    int i01 = cy1 * HW + cx0, i11 = cy1 * HW + cx1;
    const float* src = g_y + (b * 4 + i) * 64 * NPIX;
    float* dst = g_nbr + pair * 64 * NPIX;
#pragma unroll 4
    for (int c = 0; c < 64; c++) {
        const float* sc = src + c * NPIX;
        float v = __fmul_rn(w00, sc[i00]);
        v = __fadd_rn(v, __fmul_rn(w10, sc[i10]));
        v = __fadd_rn(v, __fmul_rn(w01, sc[i01]));
        v = __fadd_rn(v, __fmul_rn(w11, sc[i11]));
        dst[c * NPIX + p] = v;
    }
}

// ---------------- tiled direct 3x3 conv (SAME), NCHW fp32, FFMA2 ----------
// Block: 256 thr. Tile 16x16 pixels x 64 cout. Thread: 4 pixels x 8 cout-pairs.
// Weights prepacked float2 along cout -> fma.rn.f32x2 (2 exact fp32 FMA/inst).
template <int CIN>
__global__ __launch_bounds__(256, 2)
void conv3x3_k(const float* __restrict__ inA, int inA_stride,
               const float* __restrict__ inB, int inB_stride, int splitC,
               const float2* __restrict__ Wt2, // [COUT/2][CIN][9] float2
               const float* __restrict__ bias, // may be null
               const float* __restrict__ maskp,// per-img mask (NPIX) or null
               float* __restrict__ outp, int out_stride) {
    __shared__ float sX[8][18][20];   // padded rows -> conflict free
    __shared__ float2 sW2[32 * 72];   // 32 cout-pairs x 8 cin x 9 taps
    const int img = blockIdx.z;
    const int coutbase = blockIdx.y * 64;
    const int tx = blockIdx.x % 5, ty = blockIdx.x / 5;
    const int w0 = tx * 16, h0 = ty * 16;
    const int t = threadIdx.x;
    const int s = t & 63;
    const int wl = s & 15;     // pixel col in tile
    const int hq = s >> 4;     // row quad 0..3
    const int cg = t >> 6;     // cout group 0..3 (16 couts = 8 pairs each)

    // mask-aware tile skip: output of this conv is multiplied by maskp later;
    // if the whole 16x16 tile is masked out, its values are never used.
    if (maskp != nullptr) {
        const float* mp = maskp + (long)img * NPIX;
        int any = 0;
#pragma unroll
        for (int k = 0; k < 4; k++)
            any |= (mp[(h0 + hq * 4 + k) * HW + (w0 + wl)] != 0.0f);
        if (__syncthreads_count(any) == 0) return;
    }

    ull acc2[4][8];
#pragma unroll
    for (int k = 0; k < 4; k++)
#pragma unroll
        for (int j = 0; j < 8; j++) acc2[k][j] = 0ULL;

    for (int cin0 = 0; cin0 < CIN; cin0 += 8) {
        const float* src;
        int cbase;
        if (cin0 < splitC) { src = inA + (long)img * inA_stride; cbase = cin0; }
        else               { src = inB + (long)img * inB_stride; cbase = cin0 - splitC; }
        // stage input tile with halo: 8ci x 18 x 18
        for (int idx = t; idx < 8 * 18 * 18; idx += 256) {
            int ci = idx / 324, rem = idx % 324;
            int r = rem / 18, c = rem % 18;
            int gh = h0 - 1 + r, gw = w0 - 1 + c;
            float v = 0.0f;
            if (gh >= 0 && gh < HW && gw >= 0 && gw < HW)
                v = src[(cbase + ci) * NPIX + gh * HW + gw];
            sX[ci][r][c] = v;
        }
        // stage weights: 32 pairs x 8ci x 9 (float2)
        for (int idx = t; idx < 32 * 8 * 9; idx += 256) {
            int co2 = idx / 72, rem = idx % 72;
            sW2[co2 * 72 + rem] =
                Wt2[((blockIdx.y * 32 + co2) * CIN + cin0) * 9 + rem];
        }
        __syncthreads();
#pragma unroll 1
        for (int ci = 0; ci < 8; ci++) {
            ull xb[6][3];
#pragma unroll
            for (int rr = 0; rr < 6; rr++)
#pragma unroll
                for (int cc = 0; cc < 3; cc++)
                    xb[rr][cc] = bcast2(sX[ci][hq * 4 + rr][wl + cc]);
            const float2* wp = &sW2[(cg * 8) * 72 + ci * 9];
#pragma unroll
            for (int j = 0; j < 8; j++) {
#pragma unroll
                for (int tap = 0; tap < 9; tap++) {
                    ull w2 = *reinterpret_cast<const ull*>(&wp[j * 72 + tap]);
                    int r = tap / 3, c = tap % 3;
                    fma2(acc2[0][j], xb[0 + r][c], w2);
                    fma2(acc2[1][j], xb[1 + r][c], w2);
                    fma2(acc2[2][j], xb[2 + r][c], w2);
                    fma2(acc2[3][j], xb[3 + r][c], w2);
                }
            }
        }
        __syncthreads();
    }
#pragma unroll
    for (int j = 0; j < 8; j++) {
        int co = coutbase + cg * 16 + 2 * j;
        float bv0 = bias ? bias[co] : 0.0f;
        float bv1 = bias ? bias[co + 1] : 0.0f;
#pragma unroll
        for (int k = 0; k < 4; k++) {
            int h = h0 + hq * 4 + k, w = w0 + wl;
            float2 f = unpack2(acc2[k][j]);
            outp[(long)img * out_stride + co * NPIX + h * HW + w] = f.x + bv0;
            outp[(long)img * out_stride + (co + 1) * NPIX + h * HW + w] = f.y + bv1;
        }
    }
}

// ---------------- masked mean over i ----------------
__global__ void k_agg() {
    int bj = blockIdx.y;
    int p = blockIdx.x * 256 + threadIdx.x;
    if (p >= NPIX) return;
    int b = bj >> 2, j = bj & 3;
    float ms = g_masksum[bj * NPIX + p];
    float m[4];
#pragma unroll
    for (int i = 0; i < 4; i++)
        m[i] = g_mask[((b * 4 + i) * 4 + j) * NPIX + p];
#pragma unroll 4
    for (int c = 0; c < 64; c++) {
        float v = ms * g_ego[bj * 64 * NPIX + c * NPIX + p];
#pragma unroll
        for (int i = 0; i < 4; i++)
            v += m[i] * g_convn[((b * 4 + i) * 4 + j) * 64 * NPIX + c * NPIX + p];
        g_agg[bj * 64 * NPIX + c * NPIX + p] = 0.25f * v;
    }
}

// ---------------- GRU pointwise: y <- sigmoid(u)*tanh(c) ----------------
__global__ void k_pointwise() {
    int idx = blockIdx.x * 256 + threadIdx.x;
    int p = idx % NPIX;
    int c = (idx / NPIX) & 63;
    int bl = idx / (NPIX * 64);
    float u  = g_gru[bl * 128 * NPIX + c * NPIX + p];
    float cd = g_gru[bl * 128 * NPIX + (64 + c) * NPIX + p];
    g_y[idx] = sigmoid_acc(u) * tanh_acc(cd);
}

// ---------------- weight prepack (float2 cout-paired layouts) ----------------
__global__ void k_prepack(const float* __restrict__ msg_w,
                          const float* __restrict__ gates_w,
                          const float* __restrict__ gates_b,
                          const float* __restrict__ can_w,
                          const float* __restrict__ can_b) {
    int idx = blockIdx.x * 256 + threadIdx.x;
    if (idx < 18432) {                         // msg split: [co2][ci<64][9]
        int co2 = idx / 576, rem = idx % 576;  // rem = ci*9+tap
        int coA = 2 * co2, coB = 2 * co2 + 1;
        g_wnbr2[idx] = make_float2(msg_w[coA * 1152 + rem],
                                   msg_w[coB * 1152 + rem]);
        g_wego2[idx] = make_float2(msg_w[coA * 1152 + 576 + rem],
                                   msg_w[coB * 1152 + 576 + rem]);
        return;
    }
    int k = idx - 18432;
    if (k < 73728) {                           // gru stacked [update|cand]
        int co2 = k / 1152, rem = k % 1152;    // rem = ci*9+tap, ci<128
        int coA = 2 * co2, coB = 2 * co2 + 1;
        float wa = (coA < 64) ? gates_w[(64 + coA) * 1728 + rem]
                              : can_w[(coA - 64) * 1728 + rem];
        float wb = (coB < 64) ? gates_w[(64 + coB) * 1728 + rem]
                              : can_w[(coB - 64) * 1728 + rem];
        g_wgru2[k] = make_float2(wa, wb);
        return;
    }
    k -= 73728;
    if (k < 128)
        g_bgru[k] = (k < 64) ? gates_b[64 + k] : can_b[k - 64];
}

// ---------------- output: out[b,h,w,o] = mlp_w[o,:]·h1[b,0,:,w,79-h]+mlp_b ----
__global__ void k_out(const float* __restrict__ mlp_w,
                      const float* __restrict__ mlp_b,
                      float* __restrict__ out) {
    __shared__ float sW[64 * 65];     // sW[c*65+o] = mlp_w[o*64+c]
    __shared__ float sx[4][64];
    int t = threadIdx.x;
    for (int idx = t; idx < 4096; idx += 256) {
        int o = idx >> 6, c = idx & 63;
        sW[c * 65 + o] = mlp_w[idx];
    }
    int pix = t >> 6, o = t & 63;
    int pp = blockIdx.x * 4 + pix;    // 0 .. 2*NPIX-1
    int b = pp / NPIX, pr = pp % NPIX;
    int h = pr / HW, w = pr % HW;
    int q = w * HW + (HW - 1 - h);
    sx[pix][o] = g_y[(b * 4) * 64 * NPIX + o * NPIX + q];   // feats[:,0]
    __syncthreads();
    float acc = mlp_b[o];
#pragma unroll 8
    for (int c = 0; c < 64; c++)
        acc = fmaf(sx[pix][c], sW[c * 65 + o], acc);
    out[pp * 64 + o] = acc;
}

// ---------------- host orchestration ----------------
extern "C" void kernel_launch(void* const* d_in, const int* in_sizes, int n_in,
                              void* d_out, int out_size) {
    const float* x       = (const float*)d_in[0];
    const float* pt      = (const float*)d_in[2];
    const float* msg_w   = (const float*)d_in[4];
    const float* msg_b   = (const float*)d_in[5];
    const float* gates_w = (const float*)d_in[6];
    const float* gates_b = (const float*)d_in[7];
    const float* can_w   = (const float*)d_in[8];
    const float* can_b   = (const float*)d_in[9];
    const float* mlp_w   = (const float*)d_in[10];
    const float* mlp_b   = (const float*)d_in[11];

    float *p_y, *p_nbr, *p_convn, *p_ego, *p_agg, *p_gru, *p_mask, *p_bgru;
    float2 *p_wnbr2, *p_wego2, *p_wgru2;
    cudaGetSymbolAddress((void**)&p_y, g_y);
    cudaGetSymbolAddress((void**)&p_nbr, g_nbr);
    cudaGetSymbolAddress((void**)&p_convn, g_convn);
    cudaGetSymbolAddress((void**)&p_ego, g_ego);
    cudaGetSymbolAddress((void**)&p_agg, g_agg);
    cudaGetSymbolAddress((void**)&p_gru, g_gru);
    cudaGetSymbolAddress((void**)&p_mask, g_mask);
    cudaGetSymbolAddress((void**)&p_wnbr2, g_wnbr2);
    cudaGetSymbolAddress((void**)&p_wego2, g_wego2);
    cudaGetSymbolAddress((void**)&p_wgru2, g_wgru2);
    cudaGetSymbolAddress((void**)&p_bgru, g_bgru);

    k_minv<<<1, 32>>>(pt);
    k_prepack<<<(18432 + 73728 + 128 + 255) / 256, 256>>>(msg_w, gates_w,
                                                          gates_b, can_w, can_b);
    k_mask<<<dim3(25, NPAIR), 256>>>();
    k_masksum<<<dim3(25, NIMG), 256>>>();
    k_transform<<<(NIMG * NC * NPIX) / 256, 256>>>(x);

    for (int it = 0; it < 2; it++) {
        k_warp<<<dim3(25, NPAIR), 256>>>();
        // conv(neighbors): 32 imgs, 64->64, no bias, mask-skippable
        conv3x3_k<64><<<dim3(25, 1, NPAIR), 256>>>(
            p_nbr, 64 * NPIX, p_nbr, 0, 64, p_wnbr2, nullptr, p_mask,
            p_convn, 64 * NPIX);
        // conv(ego): 8 imgs, 64->64, + msg_b
        conv3x3_k<64><<<dim3(25, 1, NIMG), 256>>>(
            p_y, 64 * NPIX, p_y, 0, 64, p_wego2, msg_b, nullptr,
            p_ego, 64 * NPIX);
        k_agg<<<dim3(25, NIMG), 256>>>();
        // fused GRU conv: [y|agg] 128 -> [update|cand] 128
        conv3x3_k<128><<<dim3(25, 2, NIMG), 256>>>(
            p_y, 64 * NPIX, p_agg, 64 * NPIX, 64, p_wgru2, p_bgru, nullptr,
            p_gru, 128 * NPIX);
        k_pointwise<<<(NIMG * NC * NPIX) / 256, 256>>>();
    }

    k_out<<<2 * NPIX / 4, 256>>>(mlp_w, mlp_b, (float*)d_out);
}